// round 6
// baseline (speedup 1.0000x reference)
#include <cuda_runtime.h>

// MLP_RSNA6: out[b, v[g,t]] = relu(sum_i x[b, k[g,i]] * w1[i] + b1) * w2[t] + b2[t]
// B=500000, TOTAL_IN=200, GROUPS=25, IN_NUM=8, OUT=75.
//
// Dataset property (verified at runtime): k = arange(200), v = arange(75)
// (identity gather/scatter). Task t = row*25+g reads x4[2t], x4[2t+1] and
// writes out[3t..3t+2]; fully coalesced streaming, no smem staging.
//
// R6: make every LDG.128 fully contiguous across the warp (lane stride 16B,
// 4 L1 wavefronts/instr instead of 8). Lane l loads C=x4[64m+l], D=x4[64m+32+l];
// parity-selected weight half gives a partial dot; one scalar shfl_xor(.,1)
// combines lane pairs. Even lanes finalize tasks 32m+(l>>1), odd lanes
// 32m+16+(l>>1) -> all 32 tasks per warp-iter, each exactly once.

#define TPB 256
#define BATCH 4
#define WPB (TPB / 32)
#define NGROUPS 25
#define IN_NUM  8
#define NCOLS   200
#define NOUT    75

__global__ __launch_bounds__(TPB)
void mlp_rsna6_fused(const float* __restrict__ x,
                     const float* __restrict__ w1,
                     const float* __restrict__ b1,
                     const float* __restrict__ w2,
                     const float* __restrict__ b2,
                     const int* __restrict__ kidx,
                     const int* __restrict__ vidx,
                     float* __restrict__ out,
                     int B)
{
    // ---- runtime identity-permutation check (block-local, cheap) ----
    __shared__ int s_ok;
    if (threadIdx.x == 0) s_ok = 1;
    __syncthreads();
    {
        bool bad = false;
        for (int e = threadIdx.x; e < NGROUPS * IN_NUM; e += TPB)
            bad |= (__ldg(&kidx[e]) != e);
        for (int e = threadIdx.x; e < NGROUPS * 3; e += TPB)
            bad |= (__ldg(&vidx[e]) != e);
        if (bad) s_ok = 0;
    }
    __syncthreads();

    // ---- weights to registers ----
    float w1r[IN_NUM];
#pragma unroll
    for (int i = 0; i < IN_NUM; i++) w1r[i] = __ldg(&w1[i]);
    const float b1r = __ldg(&b1[0]);
    float w2r[3], b2r[3];
#pragma unroll
    for (int t = 0; t < 3; t++) { w2r[t] = __ldg(&w2[t]); b2r[t] = __ldg(&b2[t]); }

    const int lane = threadIdx.x & 31;

    if (s_ok) {
        // ================= FAST PATH (identity indices) =================
        const float4* x4 = reinterpret_cast<const float4*>(x);
        const int NT = B * NGROUPS;                       // 12.5M tasks
        const int gw = blockIdx.x * WPB + (threadIdx.x >> 5); // global warp id

        // parity-selected half of w1 (uniform per thread, no indexed array)
        const bool odd = (lane & 1);
        float ws0 = odd ? w1r[4] : w1r[0];
        float ws1 = odd ? w1r[5] : w1r[1];
        float ws2 = odd ? w1r[6] : w1r[2];
        float ws3 = odd ? w1r[7] : w1r[3];

        // this lane finalizes task 32m + ((l&1)<<4) + (l>>1) each warp-iter
        const int tofs = ((lane & 1) << 4) + (lane >> 1);

        const int m0 = gw * BATCH;     // first warp-iter index
        if (32 * (m0 + BATCH) <= NT) {
            // ---- uniform full tile: contiguous loads, no predicates ----
            float4 C[BATCH], D[BATCH];
#pragma unroll
            for (int j = 0; j < BATCH; j++) {
                int c = 64 * (m0 + j);
                C[j] = __ldcs(&x4[c + lane]);
                D[j] = __ldcs(&x4[c + 32 + lane]);
            }
#pragma unroll
            for (int j = 0; j < BATCH; j++) {
                float pC = C[j].x * ws0 + C[j].y * ws1 + C[j].z * ws2 + C[j].w * ws3;
                float pD = D[j].x * ws0 + D[j].y * ws1 + D[j].z * ws2 + D[j].w * ws3;
                float sA = pC + __shfl_xor_sync(0xFFFFFFFFu, pC, 1);
                float sB = pD + __shfl_xor_sync(0xFFFFFFFFu, pD, 1);
                float h = fmaxf((odd ? sB : sA) + b1r, 0.0f);
                int t = 32 * (m0 + j) + tofs;
                __stcs(&out[3 * t + 0], fmaf(h, w2r[0], b2r[0]));
                __stcs(&out[3 * t + 1], fmaf(h, w2r[1], b2r[1]));
                __stcs(&out[3 * t + 2], fmaf(h, w2r[2], b2r[2]));
            }
        } else {
            // ---- tail: per-task direct loads (no shuffles) ----
#pragma unroll
            for (int j = 0; j < BATCH; j++) {
                int t = 32 * (m0 + j) + tofs;
                if (t < NT) {
                    float4 a0 = __ldcs(&x4[2 * t]);
                    float4 a1 = __ldcs(&x4[2 * t + 1]);
                    float h = b1r;
                    h = fmaf(a0.x, w1r[0], h);
                    h = fmaf(a0.y, w1r[1], h);
                    h = fmaf(a0.z, w1r[2], h);
                    h = fmaf(a0.w, w1r[3], h);
                    h = fmaf(a1.x, w1r[4], h);
                    h = fmaf(a1.y, w1r[5], h);
                    h = fmaf(a1.z, w1r[6], h);
                    h = fmaf(a1.w, w1r[7], h);
                    h = fmaxf(h, 0.0f);
                    __stcs(&out[3 * t + 0], fmaf(h, w2r[0], b2r[0]));
                    __stcs(&out[3 * t + 1], fmaf(h, w2r[1], b2r[1]));
                    __stcs(&out[3 * t + 2], fmaf(h, w2r[2], b2r[2]));
                }
            }
        }
    } else {
        // ============ GENERAL FALLBACK (arbitrary indices) ============
        const int stride = gridDim.x * TPB;
        for (int r = blockIdx.x * TPB + threadIdx.x; r < B; r += stride) {
            const float* xr = x + (long long)r * NCOLS;
            float* orow = out + (long long)r * NOUT;
#pragma unroll 5
            for (int j = 0; j < NOUT; j++) orow[j] = 0.0f;
#pragma unroll 1
            for (int g = 0; g < NGROUPS; g++) {
                float h = b1r;
#pragma unroll
                for (int i = 0; i < IN_NUM; i++)
                    h = fmaf(__ldg(&xr[__ldg(&kidx[g * IN_NUM + i])]), w1r[i], h);
                h = fmaxf(h, 0.0f);
#pragma unroll
                for (int t = 0; t < 3; t++)
                    orow[__ldg(&vidx[g * 3 + t])] = fmaf(h, w2r[t], b2r[t]);
            }
        }
    }
}

extern "C" void kernel_launch(void* const* d_in, const int* in_sizes, int n_in,
                              void* d_out, int out_size)
{
    const float* x    = (const float*)d_in[0];
    const float* w1   = (const float*)d_in[1];
    const float* b1   = (const float*)d_in[2];
    const float* w2   = (const float*)d_in[3];
    const float* b2   = (const float*)d_in[4];
    const int*   kidx = (const int*)d_in[5];
    const int*   vidx = (const int*)d_in[6];
    float* out = (float*)d_out;

    const int B  = in_sizes[0] / NCOLS;
    const long long NT = (long long)B * NGROUPS;
    // one warp handles 32*BATCH tasks; single pass
    long long warps = (NT + 32LL * BATCH - 1) / (32LL * BATCH);
    int grid = (int)((warps + WPB - 1) / WPB);
    if (grid < 1) grid = 1;

    mlp_rsna6_fused<<<grid, TPB>>>(x, w1, b1, w2, b2, kidx, vidx, out, B);
}